// round 5
// baseline (speedup 1.0000x reference)
#include <cuda_runtime.h>
#include <cstdint>

// ----------------------------------------------------------------------------
// CustomConvLayer: 9 bilinear taps at integer+0.4 offsets == exact 4x4 conv
// with folded weights. FP32 compute via packed fma.rn.f32x2 (2 couts/lane).
//   x:       [8, 64, 128, 128] f32
//   weights: [64, 64, 9] f32
//   taps:    [9, 2] f32 (dy, dx)
//   out:     [8, 64, 128, 128] f32
// ----------------------------------------------------------------------------

#define B_     8
#define CIN    64
#define COUT   64
#define HW     128
#define NTAP   9

// Effective 4x4 weights, layout [cin][16 taps][cout]
__device__ float g_wEff[CIN * 16 * COUT];

__global__ void prep_weights_kernel(const float* __restrict__ w,
                                    const float* __restrict__ off) {
    int idx = blockIdx.x * blockDim.x + threadIdx.x;
    if (idx >= COUT * CIN) return;
    int o = idx >> 6;   // /64
    int i = idx & 63;
    float acc[16];
#pragma unroll
    for (int t = 0; t < 16; t++) acc[t] = 0.f;
#pragma unroll
    for (int k = 0; k < NTAP; k++) {
        float dy = off[2 * k + 0];
        float dx = off[2 * k + 1];
        float fyf = floorf(dy), fxf = floorf(dx);
        int iy = (int)fyf, ix = (int)fxf;
        float fy = dy - fyf, fx = dx - fxf;
        float wk = w[(o * CIN + i) * NTAP + k];
        acc[iy * 4 + ix]           += wk * (1.f - fy) * (1.f - fx);
        acc[iy * 4 + ix + 1]       += wk * (1.f - fy) * fx;
        acc[(iy + 1) * 4 + ix]     += wk * fy * (1.f - fx);
        acc[(iy + 1) * 4 + ix + 1] += wk * fy * fx;
    }
#pragma unroll
    for (int t = 0; t < 16; t++)
        g_wEff[(i * 16 + t) * COUT + o] = acc[t];
}

// ---------------- packed f32x2 helpers ----------------
__device__ __forceinline__ unsigned long long pkdup(float v) {
    unsigned long long r;
    asm("mov.b64 %0, {%1, %1};" : "=l"(r) : "f"(v));
    return r;
}
__device__ __forceinline__ void ffma2(unsigned long long& d,
                                      unsigned long long a,
                                      unsigned long long b) {
    asm("fma.rn.f32x2 %0, %1, %2, %0;" : "+l"(d) : "l"(a), "l"(b));
}
__device__ __forceinline__ void unpk(unsigned long long v, float& lo, float& hi) {
    asm("mov.b64 {%0, %1}, %2;" : "=f"(lo), "=f"(hi) : "l"(v));
}

// Tile: 16 (x) x 8 (y) pixels, all 64 couts per block. 256 threads.
// Thread: 4 couts (2 packed pairs) x (2 rows x 4 cols) pixels = 32 outputs.
#define TILE_W   16
#define TILE_H   8
#define CK       8            // cin chunk
#define IN_ROWS  (TILE_H + 3) // 11
#define IN_PITCH 24           // padded row stride (conflict-free, 16B-aligned)

__global__ __launch_bounds__(256, 2)
void conv4x4_kernel(const float* __restrict__ x, float* __restrict__ out) {
    __shared__ __align__(16) float SIN[CK][IN_ROWS][IN_PITCH];   // 8448 B
    __shared__ __align__(16) float SW[CK][16][COUT];             // 32768 B

    const int tid = threadIdx.x;
    const int b   = blockIdx.z;
    const int gy0 = blockIdx.y * TILE_H;
    const int gx0 = blockIdx.x * TILE_W;

    const int cog = tid >> 4;        // 0..15 -> couts [4*cog, 4*cog+4)
    const int sp  = tid & 15;
    const int rp  = sp >> 2;         // 0..3 -> pixel rows 2*rp, 2*rp+1
    const int xq  = sp & 3;          // x0 = 4*xq
    const int x0  = xq * 4;
    const int rb  = rp * 2;

    unsigned long long acc[2][2][4]; // [pixel row][cout pair][px]
#pragma unroll
    for (int a0 = 0; a0 < 2; a0++)
#pragma unroll
        for (int a1 = 0; a1 < 2; a1++)
#pragma unroll
            for (int a2 = 0; a2 < 4; a2++) acc[a0][a1][a2] = 0ull;

    const float* xb = x + (size_t)b * CIN * HW * HW;

    for (int c0 = 0; c0 < CIN; c0 += CK) {
        __syncthreads();  // protect previous iteration's reads

        // ---- load input patch: CK x 11 x 24 (cols 19..23 never read) ----
        for (int l = tid; l < CK * IN_ROWS * IN_PITCH; l += 256) {
            int ci = l / (IN_ROWS * IN_PITCH);
            int rm = l - ci * (IN_ROWS * IN_PITCH);
            int r  = rm / IN_PITCH;
            int c  = rm - r * IN_PITCH;
            int gy = gy0 + r - 1;
            int gx = gx0 + c - 1;
            float v = 0.f;
            if ((unsigned)gy < (unsigned)HW && (unsigned)gx < (unsigned)HW)
                v = xb[((size_t)(c0 + ci) * HW + gy) * HW + gx];
            SIN[ci][r][c] = v;
        }
        // ---- load weights: CK*16*64 floats = 2048 float4 ----
        {
            const float4* wsrc = (const float4*)(g_wEff + (size_t)c0 * 16 * COUT);
            float4* wdst = (float4*)&SW[0][0][0];
            for (int l = tid; l < (CK * 16 * COUT) / 4; l += 256)
                wdst[l] = wsrc[l];
        }
        __syncthreads();

        for (int ci = 0; ci < CK; ci++) {
            // pack two current input rows (duplicated halves), 7 cols each
            unsigned long long P0[7], P1[7];
            {
                float4 a = *(const float4*)&SIN[ci][rb + 0][x0];
                float4 bq = *(const float4*)&SIN[ci][rb + 0][x0 + 4];
                P0[0] = pkdup(a.x);  P0[1] = pkdup(a.y);  P0[2] = pkdup(a.z);
                P0[3] = pkdup(a.w);  P0[4] = pkdup(bq.x); P0[5] = pkdup(bq.y);
                P0[6] = pkdup(bq.z);
            }
            {
                float4 a = *(const float4*)&SIN[ci][rb + 1][x0];
                float4 bq = *(const float4*)&SIN[ci][rb + 1][x0 + 4];
                P1[0] = pkdup(a.x);  P1[1] = pkdup(a.y);  P1[2] = pkdup(a.z);
                P1[3] = pkdup(a.w);  P1[4] = pkdup(bq.x); P1[5] = pkdup(bq.y);
                P1[6] = pkdup(bq.z);
            }
#pragma unroll
            for (int dy = 0; dy < 4; dy++) {
#pragma unroll
                for (int dx = 0; dx < 4; dx++) {
                    // two packed cout-pairs for this tap: couts 4cog..4cog+3
                    ulonglong2 wp =
                        *(const ulonglong2*)&SW[ci][dy * 4 + dx][cog * 4];
#pragma unroll
                    for (int px = 0; px < 4; px++) {
                        ffma2(acc[0][0][px], wp.x, P0[dx + px]);
                        ffma2(acc[0][1][px], wp.y, P0[dx + px]);
                        ffma2(acc[1][0][px], wp.x, P1[dx + px]);
                        ffma2(acc[1][1][px], wp.y, P1[dx + px]);
                    }
                }
                if (dy < 3) {
#pragma unroll
                    for (int q = 0; q < 7; q++) P0[q] = P1[q];
                    float4 a = *(const float4*)&SIN[ci][rb + dy + 2][x0];
                    float4 bq = *(const float4*)&SIN[ci][rb + dy + 2][x0 + 4];
                    P1[0] = pkdup(a.x);  P1[1] = pkdup(a.y);  P1[2] = pkdup(a.z);
                    P1[3] = pkdup(a.w);  P1[4] = pkdup(bq.x); P1[5] = pkdup(bq.y);
                    P1[6] = pkdup(bq.z);
                }
            }
        }
    }

    // ---- epilogue: unpack and store (float4 per cout-row) ----
#pragma unroll
    for (int pr = 0; pr < 2; pr++) {
        const int gy = gy0 + rb + pr;
#pragma unroll
        for (int pc = 0; pc < 2; pc++) {
            float lo[4], hi[4];
#pragma unroll
            for (int px = 0; px < 4; px++) unpk(acc[pr][pc][px], lo[px], hi[px]);
            const int co = cog * 4 + pc * 2;
            float4* o0 = (float4*)&out[(((size_t)b * COUT + co) * HW + gy) * HW +
                                       gx0 + x0];
            float4* o1 = (float4*)&out[(((size_t)b * COUT + co + 1) * HW + gy) * HW +
                                       gx0 + x0];
            *o0 = make_float4(lo[0], lo[1], lo[2], lo[3]);
            *o1 = make_float4(hi[0], hi[1], hi[2], hi[3]);
        }
    }
}

extern "C" void kernel_launch(void* const* d_in, const int* in_sizes, int n_in,
                              void* d_out, int out_size) {
    const float* x   = (const float*)d_in[0];
    const float* w   = (const float*)d_in[1];
    const float* off = (const float*)d_in[2];
    float* out = (float*)d_out;

    prep_weights_kernel<<<(COUT * CIN + 255) / 256, 256>>>(w, off);

    dim3 grid(HW / TILE_W, HW / TILE_H, B_);  // (8, 16, 8)
    conv4x4_kernel<<<grid, 256>>>(x, out);
}

// round 7
// speedup vs baseline: 1.0278x; 1.0278x over previous
#include <cuda_runtime.h>
#include <cuda_bf16.h>
#include <cstdint>

// ============================================================================
// CustomConvLayer: 9 bilinear taps @ integer+0.4 == exact 4x4 conv (folded).
// HMMA (mma.sync m16n8k16 bf16) implicit GEMM, bf16x3 split for fp32 accuracy.
// (tcgen05 unavailable: harness compiles compute_103 PTX, no 'a' features.)
//   x: [8,64,128,128] f32   w: [64,64,9] f32   taps: [9,2] f32
//   out: [8,64,128,128] f32
// ============================================================================

#define B_    8
#define CIN   64
#define COUT  64
#define HW    128
#define NTAP  9

// pixel tile per CTA: 8 (y) x 16 (x); patch 11 x 19 pixels
#define TY 8
#define TX 16
#define IY 11
#define IX 19
#define NPX (IY * IX)            // 209
#define PITCH 48                 // bytes per pixel row (16 bf16 = 32B data, padded)
#define PHALF (NPX * PITCH)      // 10032 B per half (hi / lo)

// bf16 split weights: [16 taps][cout][cin]
__device__ __nv_bfloat16 g_whi[16 * COUT * CIN];
__device__ __nv_bfloat16 g_wlo[16 * COUT * CIN];

// ---------------------------------------------------------------------------
__global__ void prep_weights_kernel(const float* __restrict__ w,
                                    const float* __restrict__ off) {
    int idx = blockIdx.x * blockDim.x + threadIdx.x;
    if (idx >= COUT * CIN) return;
    int o = idx >> 6, i = idx & 63;
    float acc[16];
#pragma unroll
    for (int t = 0; t < 16; t++) acc[t] = 0.f;
#pragma unroll
    for (int k = 0; k < NTAP; k++) {
        float dy = off[2 * k + 0];
        float dx = off[2 * k + 1];
        float fyf = floorf(dy), fxf = floorf(dx);
        int iy = (int)fyf, ix = (int)fxf;
        float fy = dy - fyf, fx = dx - fxf;
        float wk = w[(o * CIN + i) * NTAP + k];
        acc[iy * 4 + ix]           += wk * (1.f - fy) * (1.f - fx);
        acc[iy * 4 + ix + 1]       += wk * (1.f - fy) * fx;
        acc[(iy + 1) * 4 + ix]     += wk * fy * (1.f - fx);
        acc[(iy + 1) * 4 + ix + 1] += wk * fy * fx;
    }
#pragma unroll
    for (int t = 0; t < 16; t++) {
        float v = acc[t];
        __nv_bfloat16 h = __float2bfloat16(v);
        __nv_bfloat16 l = __float2bfloat16(v - __bfloat162float(h));
        g_whi[(t * COUT + o) * CIN + i] = h;
        g_wlo[(t * COUT + o) * CIN + i] = l;
    }
}

// ---------------------------------------------------------------------------
__device__ __forceinline__ uint32_t smem_to_u32(const void* p) {
    uint32_t a;
    asm("{ .reg .u64 t; cvta.to.shared.u64 t, %1; cvt.u32.u64 %0, t; }"
        : "=r"(a) : "l"(p));
    return a;
}

#define LDSM4(r, addr) \
    asm volatile("ldmatrix.sync.aligned.m8n8.x4.shared.b16 {%0,%1,%2,%3}, [%4];" \
                 : "=r"((r)[0]), "=r"((r)[1]), "=r"((r)[2]), "=r"((r)[3]) \
                 : "r"(addr))

#define MMA16816(c, a, bb) \
    asm("mma.sync.aligned.m16n8k16.row.col.f32.bf16.bf16.f32 " \
        "{%0,%1,%2,%3}, {%4,%5,%6,%7}, {%8,%9}, {%0,%1,%2,%3};" \
        : "+f"((c)[0]), "+f"((c)[1]), "+f"((c)[2]), "+f"((c)[3]) \
        : "r"((a)[0]), "r"((a)[1]), "r"((a)[2]), "r"((a)[3]), \
          "r"((bb)[0]), "r"((bb)[1]))

// Load B fragments (4 n8-tiles x hi/lo) for one (tap, chunk).
// b-frag layout (m16n8k16): b0 = {k=tig*2, tig*2+1}, b1 = {k=tig*2+8, +9}, n = g.
__device__ __forceinline__ void load_b(int tap, int chunk, int nbase,
                                       int g, int tig,
                                       uint32_t bh[4][2], uint32_t bl[4][2]) {
    const int kofs = chunk * 16 + tig * 2;
#pragma unroll
    for (int nb = 0; nb < 4; nb++) {
        int n = nbase + nb * 8 + g;
        int base = (tap * COUT + n) * CIN + kofs;
        bh[nb][0] = *(const uint32_t*)(g_whi + base);
        bh[nb][1] = *(const uint32_t*)(g_whi + base + 8);
        bl[nb][0] = *(const uint32_t*)(g_wlo + base);
        bl[nb][1] = *(const uint32_t*)(g_wlo + base + 8);
    }
}

// ---------------------------------------------------------------------------
// 256 threads, 8 warps. Warp w: y rows {2*(w%4), 2*(w%4)+1}, couts (w/4)*32..+31.
// ---------------------------------------------------------------------------
__global__ __launch_bounds__(256, 2)
void conv_hmma_kernel(const float* __restrict__ x, float* __restrict__ out) {
    __shared__ __align__(16) char patch[2 * PHALF];   // hi then lo, 20064 B

    const int tid  = threadIdx.x;
    const int lane = tid & 31;
    const int w    = tid >> 5;
    const int wy   = w & 3;                 // y-pair index
    const int nbase = (w >> 2) * 32;        // cout half
    const int g   = lane >> 2;
    const int tig = lane & 3;

    const int b  = blockIdx.z;
    const int y0 = blockIdx.y * TY;
    const int x0 = blockIdx.x * TX;

    const uint32_t sbase = smem_to_u32(patch);
    // ldmatrix x4 address pattern: t0-7 rows0-7 col0 | t8-15 rows8-15 col0 |
    //                              t16-23 rows0-7 col8 | t24-31 rows8-15 col8
    const uint32_t laneoff =
        (uint32_t)(((lane & 7) + ((lane >> 3) & 1) * 8) * PITCH + (lane >> 4) * 16);

    float acc[2][4][4];
#pragma unroll
    for (int m = 0; m < 2; m++)
#pragma unroll
        for (int nb = 0; nb < 4; nb++)
#pragma unroll
            for (int q = 0; q < 4; q++) acc[m][nb][q] = 0.f;

    const float* xb = x + (size_t)b * CIN * HW * HW;

    for (int chunk = 0; chunk < 4; chunk++) {
        __syncthreads();   // protect previous chunk's reads
        // ---- stage patch: 16 cin x 209 px, fp32 -> bf16 hi/lo ----
        for (int idx = tid; idx < 16 * NPX; idx += 256) {
            int cl = idx / NPX;
            int px = idx - cl * NPX;
            int py = px / IX, pxx = px - py * IX;
            int gy = y0 + py - 1, gx = x0 + pxx - 1;
            float v = 0.f;
            if ((unsigned)gy < (unsigned)HW && (unsigned)gx < (unsigned)HW)
                v = xb[((size_t)(chunk * 16 + cl) * HW + gy) * HW + gx];
            __nv_bfloat16 h = __float2bfloat16(v);
            __nv_bfloat16 l = __float2bfloat16(v - __bfloat162float(h));
            *(__nv_bfloat16*)(patch + px * PITCH + cl * 2) = h;
            *(__nv_bfloat16*)(patch + PHALF + px * PITCH + cl * 2) = l;
        }
        __syncthreads();

        // ---- tap loop, B double-buffered in registers ----
        uint32_t bh[2][4][2], bl[2][4][2];
        load_b(0, chunk, nbase, g, tig, bh[0], bl[0]);

#pragma unroll
        for (int tap = 0; tap < 16; tap++) {
            const int cur = tap & 1;
            if (tap < 15)
                load_b(tap + 1, chunk, nbase, g, tig, bh[cur ^ 1], bl[cur ^ 1]);

            const int dy = tap >> 2, dx = tap & 3;
#pragma unroll
            for (int m = 0; m < 2; m++) {
                const int sy = wy * 2 + m + dy;
                const uint32_t abase =
                    sbase + (uint32_t)((sy * IX + dx) * PITCH) + laneoff;
                uint32_t ah[4], al[4];
                LDSM4(ah, abase);
                LDSM4(al, abase + PHALF);
#pragma unroll
                for (int nb = 0; nb < 4; nb++) {
                    MMA16816(acc[m][nb], ah, bh[cur][nb]);
                    MMA16816(acc[m][nb], ah, bl[cur][nb]);
                    MMA16816(acc[m][nb], al, bh[cur][nb]);
                }
            }
        }
    }

    // ---- epilogue ----
    // c-frag: c0 = (x=g,   cout=tig*2), c1 = (x=g,   cout=tig*2+1)
    //         c2 = (x=g+8, cout=tig*2), c3 = (x=g+8, cout=tig*2+1)
#pragma unroll
    for (int m = 0; m < 2; m++) {
        const int gy = y0 + wy * 2 + m;
#pragma unroll
        for (int nb = 0; nb < 4; nb++) {
            const int n = nbase + nb * 8 + tig * 2;
            float* o0 = out + ((size_t)b * COUT + n) * (HW * HW) + (size_t)gy * HW;
            float* o1 = o0 + (size_t)(HW * HW);
            o0[x0 + g]     = acc[m][nb][0];
            o1[x0 + g]     = acc[m][nb][1];
            o0[x0 + g + 8] = acc[m][nb][2];
            o1[x0 + g + 8] = acc[m][nb][3];
        }
    }
}

extern "C" void kernel_launch(void* const* d_in, const int* in_sizes, int n_in,
                              void* d_out, int out_size) {
    const float* x   = (const float*)d_in[0];
    const float* w   = (const float*)d_in[1];
    const float* off = (const float*)d_in[2];
    float* out = (float*)d_out;

    prep_weights_kernel<<<(COUT * CIN + 255) / 256, 256>>>(w, off);

    dim3 grid(HW / TX, HW / TY, B_);   // (8, 16, 8) = 1024 CTAs
    conv_hmma_kernel<<<grid, 256>>>(x, out);
}

// round 8
// speedup vs baseline: 2.3556x; 2.2918x over previous
#include <cuda_runtime.h>
#include <cuda_bf16.h>
#include <cstdint>

// ============================================================================
// CustomConvLayer: 9 bilinear taps @ integer+0.4 == exact 4x4 conv (folded).
// HMMA (mma.sync m16n8k16 bf16) implicit GEMM, bf16x3 split for fp32 accuracy.
// R8: B-fragments pre-permuted in global -> 4 coalesced LDG.128 per tap per
//     warp (was 16 scattered LDG.32 -> 8x fewer L1 wavefronts on the dominant
//     traffic term).
//   x: [8,64,128,128] f32   w: [64,64,9] f32   taps: [9,2] f32
//   out: [8,64,128,128] f32
// ============================================================================

#define B_    8
#define CIN   64
#define COUT  64
#define HW    128
#define NTAP  9

// pixel tile per CTA: 8 (y) x 16 (x); patch 11 x 19 pixels
#define TY 8
#define TX 16
#define IY 11
#define IX 19
#define NPX (IY * IX)            // 209
#define PITCH 48                 // bytes per pixel row (16 bf16 = 32B data, padded)
#define PHALF (NPX * PITCH)      // 10032 B per half (hi / lo)

// bf16 split weights (intermediate): [16 taps][cout][cin]
__device__ __nv_bfloat16 g_whi[16 * COUT * CIN];
__device__ __nv_bfloat16 g_wlo[16 * COUT * CIN];

// permuted per-lane fragments: [tap][chunk][nh][part(4)][lane(32)] of uint4
//  part0/1 = hi (nb 0,1 / nb 2,3), part2/3 = lo
__device__ uint4 g_wperm[16 * 4 * 2 * 4 * 32];   // 256 KB

// ---------------------------------------------------------------------------
__global__ void prep_weights_kernel(const float* __restrict__ w,
                                    const float* __restrict__ off) {
    int idx = blockIdx.x * blockDim.x + threadIdx.x;
    if (idx >= COUT * CIN) return;
    int o = idx >> 6, i = idx & 63;
    float acc[16];
#pragma unroll
    for (int t = 0; t < 16; t++) acc[t] = 0.f;
#pragma unroll
    for (int k = 0; k < NTAP; k++) {
        float dy = off[2 * k + 0];
        float dx = off[2 * k + 1];
        float fyf = floorf(dy), fxf = floorf(dx);
        int iy = (int)fyf, ix = (int)fxf;
        float fy = dy - fyf, fx = dx - fxf;
        float wk = w[(o * CIN + i) * NTAP + k];
        acc[iy * 4 + ix]           += wk * (1.f - fy) * (1.f - fx);
        acc[iy * 4 + ix + 1]       += wk * (1.f - fy) * fx;
        acc[(iy + 1) * 4 + ix]     += wk * fy * (1.f - fx);
        acc[(iy + 1) * 4 + ix + 1] += wk * fy * fx;
    }
#pragma unroll
    for (int t = 0; t < 16; t++) {
        float v = acc[t];
        __nv_bfloat16 h = __float2bfloat16(v);
        __nv_bfloat16 l = __float2bfloat16(v - __bfloat162float(h));
        g_whi[(t * COUT + o) * CIN + i] = h;
        g_wlo[(t * COUT + o) * CIN + i] = l;
    }
}

// b-frag layout (m16n8k16.col): lane (g=lane>>2, tig=lane&3) needs, for each
// n8 tile nb:  b0 = u32 @ w[n][k0],  b1 = u32 @ w[n][k0+8],
// with n = nh*32 + nb*8 + g, k0 = chunk*16 + tig*2.  (validated in R7)
__global__ void prep_perm_kernel() {
    int idx = blockIdx.x * blockDim.x + threadIdx.x;
    if (idx >= 16 * 4 * 2 * 32) return;
    int lane  = idx & 31;
    int nh    = (idx >> 5) & 1;
    int chunk = (idx >> 6) & 3;
    int tap   = idx >> 8;
    int g = lane >> 2, tig = lane & 3;
    int kofs = chunk * 16 + tig * 2;
    uint32_t h[8], l[8];
#pragma unroll
    for (int nb = 0; nb < 4; nb++) {
        int n = nh * 32 + nb * 8 + g;
        int base = (tap * COUT + n) * CIN + kofs;
        h[nb * 2 + 0] = *(const uint32_t*)(g_whi + base);
        h[nb * 2 + 1] = *(const uint32_t*)(g_whi + base + 8);
        l[nb * 2 + 0] = *(const uint32_t*)(g_wlo + base);
        l[nb * 2 + 1] = *(const uint32_t*)(g_wlo + base + 8);
    }
    uint4* dst = g_wperm + ((((tap * 4 + chunk) * 2 + nh) * 4) * 32) + lane;
    dst[0]  = make_uint4(h[0], h[1], h[2], h[3]);
    dst[32] = make_uint4(h[4], h[5], h[6], h[7]);
    dst[64] = make_uint4(l[0], l[1], l[2], l[3]);
    dst[96] = make_uint4(l[4], l[5], l[6], l[7]);
}

// ---------------------------------------------------------------------------
__device__ __forceinline__ uint32_t smem_to_u32(const void* p) {
    uint32_t a;
    asm("{ .reg .u64 t; cvta.to.shared.u64 t, %1; cvt.u32.u64 %0, t; }"
        : "=r"(a) : "l"(p));
    return a;
}

#define LDSM4(r, addr) \
    asm volatile("ldmatrix.sync.aligned.m8n8.x4.shared.b16 {%0,%1,%2,%3}, [%4];" \
                 : "=r"((r)[0]), "=r"((r)[1]), "=r"((r)[2]), "=r"((r)[3]) \
                 : "r"(addr))

#define MMA16816(c, a, bb) \
    asm("mma.sync.aligned.m16n8k16.row.col.f32.bf16.bf16.f32 " \
        "{%0,%1,%2,%3}, {%4,%5,%6,%7}, {%8,%9}, {%0,%1,%2,%3};" \
        : "+f"((c)[0]), "+f"((c)[1]), "+f"((c)[2]), "+f"((c)[3]) \
        : "r"((a)[0]), "r"((a)[1]), "r"((a)[2]), "r"((a)[3]), \
          "r"((bb)[0]), "r"((bb)[1]))

// coalesced B load: 4 x LDG.128 per (tap, chunk)
__device__ __forceinline__ void load_b(const uint4* wp,
                                       uint32_t bh[4][2], uint32_t bl[4][2]) {
    uint4 h0 = wp[0], h1 = wp[32], l0 = wp[64], l1 = wp[96];
    bh[0][0] = h0.x; bh[0][1] = h0.y; bh[1][0] = h0.z; bh[1][1] = h0.w;
    bh[2][0] = h1.x; bh[2][1] = h1.y; bh[3][0] = h1.z; bh[3][1] = h1.w;
    bl[0][0] = l0.x; bl[0][1] = l0.y; bl[1][0] = l0.z; bl[1][1] = l0.w;
    bl[2][0] = l1.x; bl[2][1] = l1.y; bl[3][0] = l1.z; bl[3][1] = l1.w;
}

// ---------------------------------------------------------------------------
// 256 threads, 8 warps. Warp w: y rows {2*(w%4), 2*(w%4)+1}, couts (w/4)*32..+31.
// ---------------------------------------------------------------------------
__global__ __launch_bounds__(256, 2)
void conv_hmma_kernel(const float* __restrict__ x, float* __restrict__ out) {
    __shared__ __align__(16) char patch[2 * PHALF];   // hi then lo, 20064 B

    const int tid  = threadIdx.x;
    const int lane = tid & 31;
    const int w    = tid >> 5;
    const int wy   = w & 3;                 // y-pair index
    const int nh   = w >> 2;                // cout half
    const int nbase = nh * 32;
    const int g   = lane >> 2;
    const int tig = lane & 3;

    const int b  = blockIdx.z;
    const int y0 = blockIdx.y * TY;
    const int x0 = blockIdx.x * TX;

    const uint32_t sbase = smem_to_u32(patch);
    const uint32_t laneoff =
        (uint32_t)(((lane & 7) + ((lane >> 3) & 1) * 8) * PITCH + (lane >> 4) * 16);

    float acc[2][4][4];
#pragma unroll
    for (int m = 0; m < 2; m++)
#pragma unroll
        for (int nb = 0; nb < 4; nb++)
#pragma unroll
            for (int q = 0; q < 4; q++) acc[m][nb][q] = 0.f;

    const float* xb = x + (size_t)b * CIN * HW * HW;

    for (int chunk = 0; chunk < 4; chunk++) {
        __syncthreads();   // protect previous chunk's reads
        // ---- stage patch: 16 cin x 209 px, fp32 -> bf16 hi/lo ----
        for (int idx = tid; idx < 16 * NPX; idx += 256) {
            int cl = idx / NPX;
            int px = idx - cl * NPX;
            int py = px / IX, pxx = px - py * IX;
            int gy = y0 + py - 1, gx = x0 + pxx - 1;
            float v = 0.f;
            if ((unsigned)gy < (unsigned)HW && (unsigned)gx < (unsigned)HW)
                v = xb[((size_t)(chunk * 16 + cl) * HW + gy) * HW + gx];
            __nv_bfloat16 h = __float2bfloat16(v);
            __nv_bfloat16 l = __float2bfloat16(v - __bfloat162float(h));
            *(__nv_bfloat16*)(patch + px * PITCH + cl * 2) = h;
            *(__nv_bfloat16*)(patch + PHALF + px * PITCH + cl * 2) = l;
        }
        __syncthreads();

        // per-warp base into permuted weights for this chunk
        const uint4* wp0 = g_wperm + (((0 * 4 + chunk) * 2 + nh) * 4) * 32 + lane;
        // stride between taps in uint4 units: 4*2*4*32 = 1024
        #define TAPSTRIDE 1024

        // ---- tap loop, B double-buffered in registers ----
        uint32_t bh[2][4][2], bl[2][4][2];
        load_b(wp0, bh[0], bl[0]);

#pragma unroll
        for (int tap = 0; tap < 16; tap++) {
            const int cur = tap & 1;
            if (tap < 15)
                load_b(wp0 + (tap + 1) * TAPSTRIDE, bh[cur ^ 1], bl[cur ^ 1]);

            const int dy = tap >> 2, dx = tap & 3;
#pragma unroll
            for (int m = 0; m < 2; m++) {
                const int sy = wy * 2 + m + dy;
                const uint32_t abase =
                    sbase + (uint32_t)((sy * IX + dx) * PITCH) + laneoff;
                uint32_t ah[4], al[4];
                LDSM4(ah, abase);
                LDSM4(al, abase + PHALF);
#pragma unroll
                for (int nb = 0; nb < 4; nb++) {
                    MMA16816(acc[m][nb], ah, bh[cur][nb]);
                    MMA16816(acc[m][nb], ah, bl[cur][nb]);
                    MMA16816(acc[m][nb], al, bh[cur][nb]);
                }
            }
        }
    }

    // ---- epilogue ----
    // c-frag: c0 = (x=g,   cout=tig*2), c1 = (x=g,   cout=tig*2+1)
    //         c2 = (x=g+8, cout=tig*2), c3 = (x=g+8, cout=tig*2+1)
#pragma unroll
    for (int m = 0; m < 2; m++) {
        const int gy = y0 + wy * 2 + m;
#pragma unroll
        for (int nb = 0; nb < 4; nb++) {
            const int n = nbase + nb * 8 + tig * 2;
            float* o0 = out + ((size_t)b * COUT + n) * (HW * HW) + (size_t)gy * HW;
            float* o1 = o0 + (size_t)(HW * HW);
            o0[x0 + g]     = acc[m][nb][0];
            o1[x0 + g]     = acc[m][nb][1];
            o0[x0 + g + 8] = acc[m][nb][2];
            o1[x0 + g + 8] = acc[m][nb][3];
        }
    }
}

extern "C" void kernel_launch(void* const* d_in, const int* in_sizes, int n_in,
                              void* d_out, int out_size) {
    const float* x   = (const float*)d_in[0];
    const float* w   = (const float*)d_in[1];
    const float* off = (const float*)d_in[2];
    float* out = (float*)d_out;

    prep_weights_kernel<<<(COUT * CIN + 255) / 256, 256>>>(w, off);
    prep_perm_kernel<<<(16 * 4 * 2 * 32 + 255) / 256, 256>>>();

    dim3 grid(HW / TX, HW / TY, B_);   // (8, 16, 8) = 1024 CTAs
    conv_hmma_kernel<<<grid, 256>>>(x, out);
}